// round 1
// baseline (speedup 1.0000x reference)
#include <cuda_runtime.h>
#include <math.h>

// ---------------------------------------------------------------------------
// RadarPillarFeatureNet on GB300.
// Pass 1 (moments_kernel): accumulate 14 first + 49 second moments of the
//   masked 16-channel feature vector (two-pass trick: branch mean/var derive
//   from feature moments since the branches are linear).
// finalize_kernel: fold normalization into weights:  y' = f.(w*scale)+shift.
// Pass 2 (main_kernel): warp-per-pillar fused feature build + 4 branch GEMVs
//   + per-channel max over 32 points via padded-SMEM transpose.
// ---------------------------------------------------------------------------

namespace {
constexpr int   MPTS   = 32;
constexpr float VXc = 0.2f, VYc = 0.2f, XOFF = 0.1f, YOFF = -39.9f;
constexpr int   NMOM   = 63;
constexpr int   GRID_A = 296;   // moments kernel blocks (fixed -> deterministic)
constexpr int   WARPS_A = 8;
constexpr int   WARPS_C = 4;
constexpr int   YSTRIDE = 68;   // floats; 272B rows -> 16B aligned, min bank phases
}

__device__ float g_partials[GRID_A * NMOM];
__device__ float g_coeff[320];  // wp1[16*8] | wp2[16*2]@128 | wp3[16*2]@160 | wp4[16*4]@192 | shift[64]@256

__device__ __forceinline__ float wsum(float v) {
#pragma unroll
  for (int o = 16; o; o >>= 1) v += __shfl_xor_sync(0xffffffffu, v, o);
  return v;
}

// Build the 14 distinct masked feature channels for this lane's point.
// v[0..11] = feat[0..11], v[12]=feat14, v[13]=feat15 (feat12/13 == v0/v1).
__device__ __forceinline__ void make_feat(const float f[9], int np, float cx, float cy,
                                          int lane, float v[14]) {
  float sx = wsum(f[0]);
  float sy = wsum(f[1]);
  float sz = wsum(f[2]);
  float s3 = wsum(f[3]);
  float s4 = wsum(f[4]);
  float inv  = 1.0f / (float)np;
  float mask = (lane < np) ? 1.0f : 0.0f;
  v[0] = (f[0] - cx) * mask;
  v[1] = (f[1] - cy) * mask;
  v[2] = f[2] * mask;  v[3] = f[3] * mask;  v[4] = f[4] * mask;
  v[5] = f[5] * mask;  v[6] = f[6] * mask;  v[7] = f[7] * mask;  v[8] = f[8] * mask;
  v[9]  = (f[0] - sx * inv) * mask;
  v[10] = (f[1] - sy * inv) * mask;
  v[11] = (f[2] - sz * inv) * mask;
  v[12] = (f[3] - s3 * inv) * mask;
  v[13] = (f[4] - s4 * inv) * mask;
}

// ---------------------------------------------------------------------------
__global__ __launch_bounds__(WARPS_A * 32)
void moments_kernel(const float* __restrict__ feats, const int* __restrict__ nump,
                    const int* __restrict__ coors, int nP) {
  __shared__ float s_stage[WARPS_A][288];
  __shared__ float s_red[WARPS_A][NMOM];
  const int warp = threadIdx.x >> 5;
  const int lane = threadIdx.x & 31;

  float acc[NMOM];
#pragma unroll
  for (int i = 0; i < NMOM; i++) acc[i] = 0.f;

  const int wg = blockIdx.x * WARPS_A + warp;
  const int nw = gridDim.x * WARPS_A;
  for (int n = wg; n < nP; n += nw) {
    // cooperative coalesced stage of this pillar's 288 floats
    const float4* src = reinterpret_cast<const float4*>(feats + (size_t)n * 288);
    float4* st = reinterpret_cast<float4*>(s_stage[warp]);
    st[lane]      = src[lane];
    st[lane + 32] = src[lane + 32];
    if (lane < 8) st[lane + 64] = src[lane + 64];
    __syncwarp();
    float f[9];
#pragma unroll
    for (int c = 0; c < 9; c++) f[c] = s_stage[warp][lane * 9 + c];  // gcd(9,32)=1 -> no conflicts
    __syncwarp();

    const int   np = nump[n];
    const float cx = (float)coors[n * 4 + 3] * VXc + XOFF;
    const float cy = (float)coors[n * 4 + 2] * VYc + YOFF;
    float v[14];
    make_feat(f, np, cx, cy, lane, v);

#pragma unroll
    for (int i = 0; i < 14; i++) acc[i] += v[i];
    const int L1[8] = {0, 1, 2, 5, 6, 7, 8, 9};
    int k = 14;
#pragma unroll
    for (int i = 0; i < 8; i++)
#pragma unroll
      for (int j = i; j < 8; j++) acc[k++] += v[L1[i]] * v[L1[j]];
    acc[50] += v[3] * v[3];   acc[51] += v[3] * v[10];  acc[52] += v[10] * v[10];
    acc[53] += v[4] * v[4];   acc[54] += v[4] * v[11];  acc[55] += v[11] * v[11];
    acc[56] += v[0] * v[12];  acc[57] += v[0] * v[13];
    acc[58] += v[1] * v[12];  acc[59] += v[1] * v[13];
    acc[60] += v[12] * v[12]; acc[61] += v[12] * v[13]; acc[62] += v[13] * v[13];
  }

#pragma unroll
  for (int i = 0; i < NMOM; i++) acc[i] = wsum(acc[i]);
  if (lane == 0) {
#pragma unroll
    for (int i = 0; i < NMOM; i++) s_red[warp][i] = acc[i];
  }
  __syncthreads();
  for (int t = threadIdx.x; t < NMOM; t += blockDim.x) {
    float s = 0.f;
#pragma unroll
    for (int w = 0; w < WARPS_A; w++) s += s_red[w][t];
    g_partials[blockIdx.x * NMOM + t] = s;  // fixed order -> deterministic
  }
}

// ---------------------------------------------------------------------------
__global__ void finalize_kernel(const float* __restrict__ w1, const float* __restrict__ w2,
                                const float* __restrict__ w3, const float* __restrict__ w4,
                                const float* __restrict__ gm_, const float* __restrict__ bt_,
                                double tot) {
  __shared__ double mom[NMOM];
  const int t = threadIdx.x;
  if (t < NMOM) {
    double s = 0.0;
    for (int i = 0; i < GRID_A; i++) s += (double)g_partials[i * NMOM + t];
    mom[t] = s / tot;
  }
  __syncthreads();
  if (t >= 64) return;
  const int br = t >> 4, uu = t & 15;

  double mu = 0.0, E2 = 0.0;
  double wv[8];
  int cin, wbase;
  if (br == 0) {
    cin = 8; wbase = uu * 8;
    const int L[8] = {0, 1, 2, 5, 6, 7, 8, 9};
    for (int c = 0; c < 8; c++) wv[c] = (double)w1[uu * 8 + c];
    for (int c = 0; c < 8; c++) mu += wv[c] * mom[L[c]];
    for (int i = 0; i < 8; i++)
      for (int j = 0; j < 8; j++) {
        int a = i < j ? i : j, d = i < j ? j : i;
        E2 += wv[i] * wv[j] * mom[14 + a * 8 - a * (a - 1) / 2 + (d - a)];
      }
  } else if (br == 1) {
    cin = 2; wbase = 128 + uu * 2;
    wv[0] = (double)w2[uu * 2]; wv[1] = (double)w2[uu * 2 + 1];
    mu = wv[0] * mom[3] + wv[1] * mom[10];
    E2 = wv[0] * wv[0] * mom[50] + 2.0 * wv[0] * wv[1] * mom[51] + wv[1] * wv[1] * mom[52];
  } else if (br == 2) {
    cin = 2; wbase = 160 + uu * 2;
    wv[0] = (double)w3[uu * 2]; wv[1] = (double)w3[uu * 2 + 1];
    mu = wv[0] * mom[4] + wv[1] * mom[11];
    E2 = wv[0] * wv[0] * mom[53] + 2.0 * wv[0] * wv[1] * mom[54] + wv[1] * wv[1] * mom[55];
  } else {
    cin = 4; wbase = 192 + uu * 4;
    const int m1i[4] = {0, 1, 12, 13};
    const int S[4][4] = {{14, 15, 56, 57}, {15, 22, 58, 59}, {56, 58, 60, 61}, {57, 59, 61, 62}};
    for (int c = 0; c < 4; c++) wv[c] = (double)w4[uu * 4 + c];
    for (int c = 0; c < 4; c++) mu += wv[c] * mom[m1i[c]];
    for (int i = 0; i < 4; i++)
      for (int j = 0; j < 4; j++) E2 += wv[i] * wv[j] * mom[S[i][j]];
  }
  const double gmv = (double)gm_[br * 16 + uu];
  const double btv = (double)bt_[br * 16 + uu];
  const double var = E2 - mu * mu;
  const double invs = 1.0 / sqrt(var + (double)1e-3f);
  const double scale = gmv * invs;
  for (int c = 0; c < cin; c++) g_coeff[wbase + c] = (float)(wv[c] * scale);
  g_coeff[256 + br * 16 + uu] = (float)(btv - mu * scale);
}

// ---------------------------------------------------------------------------
__global__ __launch_bounds__(WARPS_C * 32)
void main_kernel(const float* __restrict__ feats, const int* __restrict__ nump,
                 const int* __restrict__ coors, float* __restrict__ out, int nP) {
  __shared__ float s_y[WARPS_C][MPTS * YSTRIDE];  // 34816 B
  const int warp = threadIdx.x >> 5;
  const int lane = threadIdx.x & 31;
  const int n = blockIdx.x * WARPS_C + warp;
  if (n >= nP) return;
  float* sm = s_y[warp];

  // stage pillar
  const float4* src = reinterpret_cast<const float4*>(feats + (size_t)n * 288);
  float4* st = reinterpret_cast<float4*>(sm);
  st[lane]      = src[lane];
  st[lane + 32] = src[lane + 32];
  if (lane < 8) st[lane + 64] = src[lane + 64];
  __syncwarp();
  float f[9];
#pragma unroll
  for (int c = 0; c < 9; c++) f[c] = sm[lane * 9 + c];
  __syncwarp();

  const int   np = nump[n];
  const float cx = (float)coors[n * 4 + 3] * VXc + XOFF;
  const float cy = (float)coors[n * 4 + 2] * VYc + YOFF;
  float v[14];
  make_feat(f, np, cx, cy, lane, v);

  const float* __restrict__ cf = g_coeff;
  const float x1[8] = {v[0], v[1], v[2], v[5], v[6], v[7], v[8], v[9]};
  const float x4a = v[0], x4b = v[1], x4c = v[12], x4d = v[13];
  float* row = sm + lane * YSTRIDE;

  // branch 0: 16 units, dot-8
#pragma unroll
  for (int g = 0; g < 4; g++) {
    float ya[4];
#pragma unroll
    for (int q = 0; q < 4; q++) {
      const int u = g * 4 + q;
      float a = cf[256 + u];
#pragma unroll
      for (int c = 0; c < 8; c++) a = fmaf(x1[c], cf[u * 8 + c], a);
      ya[q] = a;
    }
    *reinterpret_cast<float4*>(row + g * 4) = make_float4(ya[0], ya[1], ya[2], ya[3]);
  }
  // branch 1: dot-2 on (v3, v10)
#pragma unroll
  for (int g = 0; g < 4; g++) {
    float ya[4];
#pragma unroll
    for (int q = 0; q < 4; q++) {
      const int u = g * 4 + q;
      float a = cf[272 + u];
      a = fmaf(v[3],  cf[128 + u * 2],     a);
      a = fmaf(v[10], cf[128 + u * 2 + 1], a);
      ya[q] = a;
    }
    *reinterpret_cast<float4*>(row + 16 + g * 4) = make_float4(ya[0], ya[1], ya[2], ya[3]);
  }
  // branch 2: dot-2 on (v4, v11)
#pragma unroll
  for (int g = 0; g < 4; g++) {
    float ya[4];
#pragma unroll
    for (int q = 0; q < 4; q++) {
      const int u = g * 4 + q;
      float a = cf[288 + u];
      a = fmaf(v[4],  cf[160 + u * 2],     a);
      a = fmaf(v[11], cf[160 + u * 2 + 1], a);
      ya[q] = a;
    }
    *reinterpret_cast<float4*>(row + 32 + g * 4) = make_float4(ya[0], ya[1], ya[2], ya[3]);
  }
  // branch 3: dot-4 on (v0, v1, v12, v13)
#pragma unroll
  for (int g = 0; g < 4; g++) {
    float ya[4];
#pragma unroll
    for (int q = 0; q < 4; q++) {
      const int u = g * 4 + q;
      float a = cf[304 + u];
      a = fmaf(x4a, cf[192 + u * 4],     a);
      a = fmaf(x4b, cf[192 + u * 4 + 1], a);
      a = fmaf(x4c, cf[192 + u * 4 + 2], a);
      a = fmaf(x4d, cf[192 + u * 4 + 3], a);
      ya[q] = a;
    }
    *reinterpret_cast<float4*>(row + 48 + g * 4) = make_float4(ya[0], ya[1], ya[2], ya[3]);
  }
  __syncwarp();

  // per-channel max over the 32 points; lane owns channels (2*lane, 2*lane+1)
  float2 mx = make_float2(-1e30f, -1e30f);
#pragma unroll
  for (int m = 0; m < MPTS; m++) {
    const float2 t2 = *reinterpret_cast<const float2*>(sm + m * YSTRIDE + 2 * lane);
    mx.x = fmaxf(mx.x, t2.x);
    mx.y = fmaxf(mx.y, t2.y);
  }
  mx.x = fmaxf(mx.x, 0.f);  // relu commutes with max
  mx.y = fmaxf(mx.y, 0.f);
  reinterpret_cast<float2*>(out + (size_t)n * 64)[lane] = mx;
}

// ---------------------------------------------------------------------------
extern "C" void kernel_launch(void* const* d_in, const int* in_sizes, int n_in,
                              void* d_out, int out_size) {
  const float* feats = (const float*)d_in[0];
  const float* w1    = (const float*)d_in[1];
  const float* w2    = (const float*)d_in[2];
  const float* w3    = (const float*)d_in[3];
  const float* w4    = (const float*)d_in[4];
  const float* gmm   = (const float*)d_in[5];
  const float* bta   = (const float*)d_in[6];
  const int*   nump  = (const int*)d_in[7];
  const int*   coors = (const int*)d_in[8];
  float*       out   = (float*)d_out;

  const int nP = in_sizes[7];               // num_points element count == N
  const double tot = (double)nP * (double)MPTS;

  moments_kernel<<<GRID_A, WARPS_A * 32>>>(feats, nump, coors, nP);
  finalize_kernel<<<1, 64>>>(w1, w2, w3, w4, gmm, bta, tot);
  const int blocksC = (nP + WARPS_C - 1) / WARPS_C;
  main_kernel<<<blocksC, WARPS_C * 32>>>(feats, nump, coors, out, nP);
}

// round 3
// speedup vs baseline: 1.2192x; 1.2192x over previous
#include <cuda_runtime.h>
#include <math.h>

// ---------------------------------------------------------------------------
// RadarPillarFeatureNet on GB300.
// Pass 1 (moments_kernel): cp.async triple-buffered accumulation of 14 first
//   + 49 second moments of the masked 16-ch feature vector.
// finalize_kernel: fold layernorm into weights: y' = f.(w*scale) + shift,
//   stored in unit-PAIR-packed layout for f32x2 math.
// Pass 2 (main_kernel): warp-per-pillar fused feature build + 4 branch GEMVs
//   with fma.rn.f32x2 (coeffs staged in SMEM), per-channel max via padded
//   SMEM transpose with float4 column reads + pair shuffle.
// ---------------------------------------------------------------------------

typedef unsigned long long u64;

namespace {
constexpr int   MPTS   = 32;
constexpr float VXc = 0.2f, VYc = 0.2f, XOFF = 0.1f, YOFF = -39.9f;
constexpr int   NMOM   = 63;
constexpr int   GRID_A = 296;
constexpr int   WARPS_A = 8;
constexpr int   DEPTH  = 3;     // cp.async pipeline depth (moments)
constexpr int   WARPS_C = 4;
constexpr int   YSTRIDE = 68;   // floats; 272B rows -> 16B aligned
}

__device__ float g_partials[GRID_A * NMOM];
// Packed coeff layout (float2 "u" pairs), viewed as u64[160]:
//  [0..63]    b0: pair p(0..7) x c(0..7)   -> idx p*8+c
//  [64..79]   b1: pair p x c(0..1)         -> 64 + p*2 + c
//  [80..95]   b2:                          -> 80 + p*2 + c
//  [96..127]  b3: pair p x c(0..3)         -> 96 + p*4 + c
//  [128..159] shifts: channel pair cp(0..31) -> 128 + cp
__device__ __align__(16) float g_coeff[320];

__device__ __forceinline__ u64 pk2(float a, float b) {
  u64 r; asm("mov.b64 %0, {%1,%2};" : "=l"(r) : "f"(a), "f"(b)); return r;
}
__device__ __forceinline__ u64 ffma2(u64 a, u64 b, u64 c) {
  u64 d; asm("fma.rn.f32x2 %0, %1, %2, %3;" : "=l"(d) : "l"(a), "l"(b), "l"(c)); return d;
}
__device__ __forceinline__ void cp16(unsigned s, const void* g) {
  asm volatile("cp.async.cg.shared.global [%0], [%1], 16;" :: "r"(s), "l"(g));
}

__device__ __forceinline__ float wsum(float v) {
#pragma unroll
  for (int o = 16; o; o >>= 1) v += __shfl_xor_sync(0xffffffffu, v, o);
  return v;
}

__device__ __forceinline__ void make_feat(const float f[9], int np, float cx, float cy,
                                          int lane, float v[14]) {
  float sx = wsum(f[0]);
  float sy = wsum(f[1]);
  float sz = wsum(f[2]);
  float s3 = wsum(f[3]);
  float s4 = wsum(f[4]);
  float inv  = 1.0f / (float)np;
  float mask = (lane < np) ? 1.0f : 0.0f;
  v[0] = (f[0] - cx) * mask;
  v[1] = (f[1] - cy) * mask;
  v[2] = f[2] * mask;  v[3] = f[3] * mask;  v[4] = f[4] * mask;
  v[5] = f[5] * mask;  v[6] = f[6] * mask;  v[7] = f[7] * mask;  v[8] = f[8] * mask;
  v[9]  = (f[0] - sx * inv) * mask;
  v[10] = (f[1] - sy * inv) * mask;
  v[11] = (f[2] - sz * inv) * mask;
  v[12] = (f[3] - s3 * inv) * mask;
  v[13] = (f[4] - s4 * inv) * mask;
}

// ---------------------------------------------------------------------------
__global__ __launch_bounds__(WARPS_A * 32)
void moments_kernel(const float* __restrict__ feats, const int* __restrict__ nump,
                    const int* __restrict__ coors, int nP) {
  __shared__ __align__(16) float s_stage[WARPS_A][DEPTH][288];
  __shared__ float s_red[WARPS_A][NMOM];
  const int warp = threadIdx.x >> 5;
  const int lane = threadIdx.x & 31;

  float acc[NMOM];
#pragma unroll
  for (int i = 0; i < NMOM; i++) acc[i] = 0.f;

  const int wg = blockIdx.x * WARPS_A + warp;
  const int nw = gridDim.x * WARPS_A;

  // prologue: fill DEPTH-1 stages
#pragma unroll
  for (int s = 0; s < DEPTH - 1; s++) {
    int n = wg + s * nw;
    if (n < nP) {
      const float4* src = reinterpret_cast<const float4*>(feats + (size_t)n * 288);
      unsigned base = (unsigned)__cvta_generic_to_shared(&s_stage[warp][s][0]);
      cp16(base + lane * 16, src + lane);
      cp16(base + (lane + 32) * 16, src + lane + 32);
      if (lane < 8) cp16(base + (lane + 64) * 16, src + lane + 64);
    }
    asm volatile("cp.async.commit_group;");
  }

  int slot = 0;
  for (int n = wg; n < nP; n += nw) {
    const int   np = nump[n];
    const float cx = (float)coors[n * 4 + 3] * VXc + XOFF;
    const float cy = (float)coors[n * 4 + 2] * VYc + YOFF;

    const int nn = n + (DEPTH - 1) * nw;
    if (nn < nP) {
      const int ws = (slot + DEPTH - 1) % DEPTH;
      const float4* src = reinterpret_cast<const float4*>(feats + (size_t)nn * 288);
      unsigned base = (unsigned)__cvta_generic_to_shared(&s_stage[warp][ws][0]);
      cp16(base + lane * 16, src + lane);
      cp16(base + (lane + 32) * 16, src + lane + 32);
      if (lane < 8) cp16(base + (lane + 64) * 16, src + lane + 64);
    }
    asm volatile("cp.async.commit_group;");
    asm volatile("cp.async.wait_group %0;" :: "n"(DEPTH - 1));
    __syncwarp();

    const float* sb = s_stage[warp][slot];
    float f[9];
#pragma unroll
    for (int c = 0; c < 9; c++) f[c] = sb[lane * 9 + c];  // gcd(9,32)=1 -> conflict-free

    float v[14];
    make_feat(f, np, cx, cy, lane, v);

#pragma unroll
    for (int i = 0; i < 14; i++) acc[i] += v[i];
    const int L1[8] = {0, 1, 2, 5, 6, 7, 8, 9};
    int k = 14;
#pragma unroll
    for (int i = 0; i < 8; i++)
#pragma unroll
      for (int j = i; j < 8; j++) acc[k++] += v[L1[i]] * v[L1[j]];
    acc[50] += v[3] * v[3];   acc[51] += v[3] * v[10];  acc[52] += v[10] * v[10];
    acc[53] += v[4] * v[4];   acc[54] += v[4] * v[11];  acc[55] += v[11] * v[11];
    acc[56] += v[0] * v[12];  acc[57] += v[0] * v[13];
    acc[58] += v[1] * v[12];  acc[59] += v[1] * v[13];
    acc[60] += v[12] * v[12]; acc[61] += v[12] * v[13]; acc[62] += v[13] * v[13];

    __syncwarp();  // all lanes done reading slot before it is refilled
    slot = (slot + 1) % DEPTH;
  }

#pragma unroll
  for (int i = 0; i < NMOM; i++) acc[i] = wsum(acc[i]);
  if (lane == 0) {
#pragma unroll
    for (int i = 0; i < NMOM; i++) s_red[warp][i] = acc[i];
  }
  __syncthreads();
  for (int t = threadIdx.x; t < NMOM; t += blockDim.x) {
    float s = 0.f;
#pragma unroll
    for (int w = 0; w < WARPS_A; w++) s += s_red[w][t];
    g_partials[blockIdx.x * NMOM + t] = s;  // fixed order -> deterministic
  }
}

// ---------------------------------------------------------------------------
__global__ void finalize_kernel(const float* __restrict__ w1, const float* __restrict__ w2,
                                const float* __restrict__ w3, const float* __restrict__ w4,
                                const float* __restrict__ gm_, const float* __restrict__ bt_,
                                double tot) {
  __shared__ double mom[NMOM];
  const int t = threadIdx.x;
  if (t < NMOM) {
    double s = 0.0;
    for (int i = 0; i < GRID_A; i++) s += (double)g_partials[i * NMOM + t];
    mom[t] = s / tot;
  }
  __syncthreads();
  if (t >= 64) return;
  const int br = t >> 4, uu = t & 15;

  double mu = 0.0, E2 = 0.0;
  double wv[8];
  int cin;
  if (br == 0) {
    cin = 8;
    const int L[8] = {0, 1, 2, 5, 6, 7, 8, 9};
    for (int c = 0; c < 8; c++) wv[c] = (double)w1[uu * 8 + c];
    for (int c = 0; c < 8; c++) mu += wv[c] * mom[L[c]];
    for (int i = 0; i < 8; i++)
      for (int j = 0; j < 8; j++) {
        int a = i < j ? i : j, d = i < j ? j : i;
        E2 += wv[i] * wv[j] * mom[14 + a * 8 - a * (a - 1) / 2 + (d - a)];
      }
  } else if (br == 1) {
    cin = 2;
    wv[0] = (double)w2[uu * 2]; wv[1] = (double)w2[uu * 2 + 1];
    mu = wv[0] * mom[3] + wv[1] * mom[10];
    E2 = wv[0] * wv[0] * mom[50] + 2.0 * wv[0] * wv[1] * mom[51] + wv[1] * wv[1] * mom[52];
  } else if (br == 2) {
    cin = 2;
    wv[0] = (double)w3[uu * 2]; wv[1] = (double)w3[uu * 2 + 1];
    mu = wv[0] * mom[4] + wv[1] * mom[11];
    E2 = wv[0] * wv[0] * mom[53] + 2.0 * wv[0] * wv[1] * mom[54] + wv[1] * wv[1] * mom[55];
  } else {
    cin = 4;
    const int m1i[4] = {0, 1, 12, 13};
    const int S[4][4] = {{14, 15, 56, 57}, {15, 22, 58, 59}, {56, 58, 60, 61}, {57, 59, 61, 62}};
    for (int c = 0; c < 4; c++) wv[c] = (double)w4[uu * 4 + c];
    for (int c = 0; c < 4; c++) mu += wv[c] * mom[m1i[c]];
    for (int i = 0; i < 4; i++)
      for (int j = 0; j < 4; j++) E2 += wv[i] * wv[j] * mom[S[i][j]];
  }
  const double gmv = (double)gm_[br * 16 + uu];
  const double btv = (double)bt_[br * 16 + uu];
  const double var = E2 - mu * mu;
  const double invs = 1.0 / sqrt(var + (double)1e-3f);
  const double scale = gmv * invs;

  // packed (unit-pair) layout writes
  const int half = uu & 1, p = uu >> 1;
  for (int c = 0; c < cin; c++) {
    int pidx;
    if      (br == 0) pidx = p * 8 + c;
    else if (br == 1) pidx = 64 + p * 2 + c;
    else if (br == 2) pidx = 80 + p * 2 + c;
    else              pidx = 96 + p * 4 + c;
    g_coeff[pidx * 2 + half] = (float)(wv[c] * scale);
  }
  g_coeff[256 + br * 16 + uu] = (float)(btv - mu * scale);  // == (128 + ch/2)*2 + (ch&1)
}

// ---------------------------------------------------------------------------
__global__ __launch_bounds__(WARPS_C * 32)
void main_kernel(const float* __restrict__ feats, const int* __restrict__ nump,
                 const int* __restrict__ coors, float* __restrict__ out, int nP) {
  __shared__ float s_y[WARPS_C][MPTS * YSTRIDE];   // 34816 B
  __shared__ __align__(16) u64 s_cf[160];          // packed coeffs
  const int tid  = threadIdx.x;
  const int warp = tid >> 5;
  const int lane = tid & 31;

  // FIX (round 2 bug): block has 128 threads; stage all 160 u64 with a stride loop.
#pragma unroll
  for (int i = tid; i < 160; i += WARPS_C * 32)
    s_cf[i] = reinterpret_cast<const u64*>(g_coeff)[i];
  __syncthreads();

  const int n = blockIdx.x * WARPS_C + warp;
  if (n >= nP) return;
  float* sm = s_y[warp];

  // stage pillar (288 floats)
  const float4* src = reinterpret_cast<const float4*>(feats + (size_t)n * 288);
  float4* st = reinterpret_cast<float4*>(sm);
  st[lane]      = src[lane];
  st[lane + 32] = src[lane + 32];
  if (lane < 8) st[lane + 64] = src[lane + 64];
  __syncwarp();
  float f[9];
#pragma unroll
  for (int c = 0; c < 9; c++) f[c] = sm[lane * 9 + c];
  __syncwarp();

  const int   np = nump[n];
  const float cx = (float)coors[n * 4 + 3] * VXc + XOFF;
  const float cy = (float)coors[n * 4 + 2] * VYc + YOFF;
  float v[14];
  make_feat(f, np, cx, cy, lane, v);

  float* row = sm + lane * YSTRIDE;
  u64 acc[8];

  // ---- branch 0: 8 unit-pairs, 8 inputs ----
  {
    const float x1[8] = {v[0], v[1], v[2], v[5], v[6], v[7], v[8], v[9]};
    u64 xp[8];
#pragma unroll
    for (int c = 0; c < 8; c++) xp[c] = pk2(x1[c], x1[c]);
#pragma unroll
    for (int pp = 0; pp < 4; pp++) {
      ulonglong2 sh = *reinterpret_cast<const ulonglong2*>(&s_cf[128 + 2 * pp]);
      acc[2 * pp] = sh.x; acc[2 * pp + 1] = sh.y;
    }
#pragma unroll
    for (int p = 0; p < 8; p++) {
#pragma unroll
      for (int c = 0; c < 8; c += 2) {
        ulonglong2 w = *reinterpret_cast<const ulonglong2*>(&s_cf[p * 8 + c]);
        acc[p] = ffma2(xp[c], w.x, acc[p]);
        acc[p] = ffma2(xp[c + 1], w.y, acc[p]);
      }
    }
#pragma unroll
    for (int pp = 0; pp < 4; pp++) {
      ulonglong2 o; o.x = acc[2 * pp]; o.y = acc[2 * pp + 1];
      *reinterpret_cast<ulonglong2*>(row + 4 * pp) = o;
    }
  }
  // ---- branch 1: inputs (v3, v10) ----
  {
    u64 a0 = pk2(v[3], v[3]), a1 = pk2(v[10], v[10]);
#pragma unroll
    for (int pp = 0; pp < 4; pp++) {
      ulonglong2 sh = *reinterpret_cast<const ulonglong2*>(&s_cf[136 + 2 * pp]);
      acc[2 * pp] = sh.x; acc[2 * pp + 1] = sh.y;
    }
#pragma unroll
    for (int p = 0; p < 8; p++) {
      ulonglong2 w = *reinterpret_cast<const ulonglong2*>(&s_cf[64 + 2 * p]);
      acc[p] = ffma2(a0, w.x, acc[p]);
      acc[p] = ffma2(a1, w.y, acc[p]);
    }
#pragma unroll
    for (int pp = 0; pp < 4; pp++) {
      ulonglong2 o; o.x = acc[2 * pp]; o.y = acc[2 * pp + 1];
      *reinterpret_cast<ulonglong2*>(row + 16 + 4 * pp) = o;
    }
  }
  // ---- branch 2: inputs (v4, v11) ----
  {
    u64 a0 = pk2(v[4], v[4]), a1 = pk2(v[11], v[11]);
#pragma unroll
    for (int pp = 0; pp < 4; pp++) {
      ulonglong2 sh = *reinterpret_cast<const ulonglong2*>(&s_cf[144 + 2 * pp]);
      acc[2 * pp] = sh.x; acc[2 * pp + 1] = sh.y;
    }
#pragma unroll
    for (int p = 0; p < 8; p++) {
      ulonglong2 w = *reinterpret_cast<const ulonglong2*>(&s_cf[80 + 2 * p]);
      acc[p] = ffma2(a0, w.x, acc[p]);
      acc[p] = ffma2(a1, w.y, acc[p]);
    }
#pragma unroll
    for (int pp = 0; pp < 4; pp++) {
      ulonglong2 o; o.x = acc[2 * pp]; o.y = acc[2 * pp + 1];
      *reinterpret_cast<ulonglong2*>(row + 32 + 4 * pp) = o;
    }
  }
  // ---- branch 3: inputs (v0, v1, v12, v13) ----
  {
    u64 a0 = pk2(v[0], v[0]), a1 = pk2(v[1], v[1]);
    u64 a2 = pk2(v[12], v[12]), a3 = pk2(v[13], v[13]);
#pragma unroll
    for (int pp = 0; pp < 4; pp++) {
      ulonglong2 sh = *reinterpret_cast<const ulonglong2*>(&s_cf[152 + 2 * pp]);
      acc[2 * pp] = sh.x; acc[2 * pp + 1] = sh.y;
    }
#pragma unroll
    for (int p = 0; p < 8; p++) {
      ulonglong2 w01 = *reinterpret_cast<const ulonglong2*>(&s_cf[96 + 4 * p]);
      ulonglong2 w23 = *reinterpret_cast<const ulonglong2*>(&s_cf[96 + 4 * p + 2]);
      acc[p] = ffma2(a0, w01.x, acc[p]);
      acc[p] = ffma2(a1, w01.y, acc[p]);
      acc[p] = ffma2(a2, w23.x, acc[p]);
      acc[p] = ffma2(a3, w23.y, acc[p]);
    }
#pragma unroll
    for (int pp = 0; pp < 4; pp++) {
      ulonglong2 o; o.x = acc[2 * pp]; o.y = acc[2 * pp + 1];
      *reinterpret_cast<ulonglong2*>(row + 48 + 4 * pp) = o;
    }
  }
  __syncwarp();

  // per-channel max: lane pair (g = lane>>1) covers channel quad 4g..4g+3;
  // each lane scans 16 rows (its parity), then one shuffle exchange.
  {
    const int g4  = (lane >> 1) * 4;
    const int par = lane & 1;
    float m0 = -1e30f, m1 = -1e30f, m2 = -1e30f, m3 = -1e30f;
#pragma unroll
    for (int i = 0; i < 16; i++) {
      const int m = par + 2 * i;
      const float4 q = *reinterpret_cast<const float4*>(sm + m * YSTRIDE + g4);
      m0 = fmaxf(m0, q.x); m1 = fmaxf(m1, q.y);
      m2 = fmaxf(m2, q.z); m3 = fmaxf(m3, q.w);
    }
    const float k0 = par ? m2 : m0, k1 = par ? m3 : m1;
    const float s0 = par ? m0 : m2, s1 = par ? m1 : m3;
    const float r0 = __shfl_xor_sync(0xffffffffu, s0, 1);
    const float r1 = __shfl_xor_sync(0xffffffffu, s1, 1);
    float2 o;
    o.x = fmaxf(fmaxf(k0, r0), 0.f);   // relu commutes with max
    o.y = fmaxf(fmaxf(k1, r1), 0.f);
    reinterpret_cast<float2*>(out + (size_t)n * 64)[lane] = o;
  }
}

// ---------------------------------------------------------------------------
extern "C" void kernel_launch(void* const* d_in, const int* in_sizes, int n_in,
                              void* d_out, int out_size) {
  const float* feats = (const float*)d_in[0];
  const float* w1    = (const float*)d_in[1];
  const float* w2    = (const float*)d_in[2];
  const float* w3    = (const float*)d_in[3];
  const float* w4    = (const float*)d_in[4];
  const float* gmm   = (const float*)d_in[5];
  const float* bta   = (const float*)d_in[6];
  const int*   nump  = (const int*)d_in[7];
  const int*   coors = (const int*)d_in[8];
  float*       out   = (float*)d_out;

  const int nP = in_sizes[7];
  const double tot = (double)nP * (double)MPTS;

  moments_kernel<<<GRID_A, WARPS_A * 32>>>(feats, nump, coors, nP);
  finalize_kernel<<<1, 64>>>(w1, w2, w3, w4, gmm, bta, tot);
  const int blocksC = (nP + WARPS_C - 1) / WARPS_C;
  main_kernel<<<blocksC, WARPS_C * 32>>>(feats, nump, coors, out, nP);
}

// round 4
// speedup vs baseline: 1.2306x; 1.0094x over previous
#include <cuda_runtime.h>
#include <math.h>

// ---------------------------------------------------------------------------
// RadarPillarFeatureNet on GB300.
// Pass 1 (moments_kernel): cp.async 5-deep pipelined accumulation of 14 first
//   + 49 second moments of the masked 16-ch feature vector.
// finalize_kernel: fold layernorm into weights: y' = f.(w*scale) + shift,
//   stored in unit-PAIR-packed layout for f32x2 math.
// Pass 2 (main_kernel): PERSISTENT warp-per-pillar loop, double-buffered
//   cp.async feature staging, 4 branch GEMVs with fma.rn.f32x2 (coeffs in
//   SMEM), per-channel max via padded SMEM transpose.
// ---------------------------------------------------------------------------

typedef unsigned long long u64;

namespace {
constexpr int   MPTS   = 32;
constexpr float VXc = 0.2f, VYc = 0.2f, XOFF = 0.1f, YOFF = -39.9f;
constexpr int   NMOM   = 63;
constexpr int   GRID_A = 296;
constexpr int   WARPS_A = 8;
constexpr int   DEPTH_A = 5;    // moments cp.async pipeline depth
constexpr int   WARPS_C = 4;
constexpr int   BLOCKS_C = 740; // persistent: ~5 blocks/SM on 148 SMs
constexpr int   YSTRIDE = 68;   // floats; 272B rows -> 16B aligned
}

__device__ float g_partials[GRID_A * NMOM];
// Packed coeff layout (float2 "u" pairs), viewed as u64[160]:
//  [0..63]    b0: pair p(0..7) x c(0..7)   -> idx p*8+c
//  [64..79]   b1: pair p x c(0..1)         -> 64 + p*2 + c
//  [80..95]   b2:                          -> 80 + p*2 + c
//  [96..127]  b3: pair p x c(0..3)         -> 96 + p*4 + c
//  [128..159] shifts: channel pair cp(0..31) -> 128 + cp
__device__ __align__(16) float g_coeff[320];

__device__ __forceinline__ u64 pk2(float a, float b) {
  u64 r; asm("mov.b64 %0, {%1,%2};" : "=l"(r) : "f"(a), "f"(b)); return r;
}
__device__ __forceinline__ u64 ffma2(u64 a, u64 b, u64 c) {
  u64 d; asm("fma.rn.f32x2 %0, %1, %2, %3;" : "=l"(d) : "l"(a), "l"(b), "l"(c)); return d;
}
__device__ __forceinline__ void cp16(unsigned s, const void* g) {
  asm volatile("cp.async.cg.shared.global [%0], [%1], 16;" :: "r"(s), "l"(g));
}

__device__ __forceinline__ float wsum(float v) {
#pragma unroll
  for (int o = 16; o; o >>= 1) v += __shfl_xor_sync(0xffffffffu, v, o);
  return v;
}

__device__ __forceinline__ void make_feat(const float f[9], int np, float cx, float cy,
                                          int lane, float v[14]) {
  float sx = wsum(f[0]);
  float sy = wsum(f[1]);
  float sz = wsum(f[2]);
  float s3 = wsum(f[3]);
  float s4 = wsum(f[4]);
  float inv  = 1.0f / (float)np;
  float mask = (lane < np) ? 1.0f : 0.0f;
  v[0] = (f[0] - cx) * mask;
  v[1] = (f[1] - cy) * mask;
  v[2] = f[2] * mask;  v[3] = f[3] * mask;  v[4] = f[4] * mask;
  v[5] = f[5] * mask;  v[6] = f[6] * mask;  v[7] = f[7] * mask;  v[8] = f[8] * mask;
  v[9]  = (f[0] - sx * inv) * mask;
  v[10] = (f[1] - sy * inv) * mask;
  v[11] = (f[2] - sz * inv) * mask;
  v[12] = (f[3] - s3 * inv) * mask;
  v[13] = (f[4] - s4 * inv) * mask;
}

// ---------------------------------------------------------------------------
__global__ __launch_bounds__(WARPS_A * 32)
void moments_kernel(const float* __restrict__ feats, const int* __restrict__ nump,
                    const int* __restrict__ coors, int nP) {
  __shared__ __align__(16) float s_stage[WARPS_A][DEPTH_A][288];
  __shared__ float s_red[WARPS_A][NMOM];
  const int warp = threadIdx.x >> 5;
  const int lane = threadIdx.x & 31;

  float acc[NMOM];
#pragma unroll
  for (int i = 0; i < NMOM; i++) acc[i] = 0.f;

  const int wg = blockIdx.x * WARPS_A + warp;
  const int nw = gridDim.x * WARPS_A;

  // prologue: fill DEPTH_A-1 stages
#pragma unroll
  for (int s = 0; s < DEPTH_A - 1; s++) {
    int n = wg + s * nw;
    if (n < nP) {
      const float4* src = reinterpret_cast<const float4*>(feats + (size_t)n * 288);
      unsigned base = (unsigned)__cvta_generic_to_shared(&s_stage[warp][s][0]);
      cp16(base + lane * 16, src + lane);
      cp16(base + (lane + 32) * 16, src + lane + 32);
      if (lane < 8) cp16(base + (lane + 64) * 16, src + lane + 64);
    }
    asm volatile("cp.async.commit_group;");
  }

  int slot = 0;
  for (int n = wg; n < nP; n += nw) {
    const int   np = nump[n];
    const float cx = (float)coors[n * 4 + 3] * VXc + XOFF;
    const float cy = (float)coors[n * 4 + 2] * VYc + YOFF;

    const int nn = n + (DEPTH_A - 1) * nw;
    if (nn < nP) {
      const int ws = (slot + DEPTH_A - 1) % DEPTH_A;
      const float4* src = reinterpret_cast<const float4*>(feats + (size_t)nn * 288);
      unsigned base = (unsigned)__cvta_generic_to_shared(&s_stage[warp][ws][0]);
      cp16(base + lane * 16, src + lane);
      cp16(base + (lane + 32) * 16, src + lane + 32);
      if (lane < 8) cp16(base + (lane + 64) * 16, src + lane + 64);
    }
    asm volatile("cp.async.commit_group;");
    asm volatile("cp.async.wait_group %0;" :: "n"(DEPTH_A - 1));
    __syncwarp();

    const float* sb = s_stage[warp][slot];
    float f[9];
#pragma unroll
    for (int c = 0; c < 9; c++) f[c] = sb[lane * 9 + c];  // gcd(9,32)=1 -> conflict-free

    float v[14];
    make_feat(f, np, cx, cy, lane, v);

#pragma unroll
    for (int i = 0; i < 14; i++) acc[i] += v[i];
    const int L1[8] = {0, 1, 2, 5, 6, 7, 8, 9};
    int k = 14;
#pragma unroll
    for (int i = 0; i < 8; i++)
#pragma unroll
      for (int j = i; j < 8; j++) acc[k++] += v[L1[i]] * v[L1[j]];
    acc[50] += v[3] * v[3];   acc[51] += v[3] * v[10];  acc[52] += v[10] * v[10];
    acc[53] += v[4] * v[4];   acc[54] += v[4] * v[11];  acc[55] += v[11] * v[11];
    acc[56] += v[0] * v[12];  acc[57] += v[0] * v[13];
    acc[58] += v[1] * v[12];  acc[59] += v[1] * v[13];
    acc[60] += v[12] * v[12]; acc[61] += v[12] * v[13]; acc[62] += v[13] * v[13];

    __syncwarp();  // all lanes done reading slot before it is refilled
    slot = (slot + 1) % DEPTH_A;
  }

#pragma unroll
  for (int i = 0; i < NMOM; i++) acc[i] = wsum(acc[i]);
  if (lane == 0) {
#pragma unroll
    for (int i = 0; i < NMOM; i++) s_red[warp][i] = acc[i];
  }
  __syncthreads();
  for (int t = threadIdx.x; t < NMOM; t += blockDim.x) {
    float s = 0.f;
#pragma unroll
    for (int w = 0; w < WARPS_A; w++) s += s_red[w][t];
    g_partials[blockIdx.x * NMOM + t] = s;  // fixed order -> deterministic
  }
}

// ---------------------------------------------------------------------------
__global__ void finalize_kernel(const float* __restrict__ w1, const float* __restrict__ w2,
                                const float* __restrict__ w3, const float* __restrict__ w4,
                                const float* __restrict__ gm_, const float* __restrict__ bt_,
                                double tot) {
  __shared__ double mom[NMOM];
  const int t = threadIdx.x;
  if (t < NMOM) {
    double s = 0.0;
    for (int i = 0; i < GRID_A; i++) s += (double)g_partials[i * NMOM + t];
    mom[t] = s / tot;
  }
  __syncthreads();
  if (t >= 64) return;
  const int br = t >> 4, uu = t & 15;

  double mu = 0.0, E2 = 0.0;
  double wv[8];
  int cin;
  if (br == 0) {
    cin = 8;
    const int L[8] = {0, 1, 2, 5, 6, 7, 8, 9};
    for (int c = 0; c < 8; c++) wv[c] = (double)w1[uu * 8 + c];
    for (int c = 0; c < 8; c++) mu += wv[c] * mom[L[c]];
    for (int i = 0; i < 8; i++)
      for (int j = 0; j < 8; j++) {
        int a = i < j ? i : j, d = i < j ? j : i;
        E2 += wv[i] * wv[j] * mom[14 + a * 8 - a * (a - 1) / 2 + (d - a)];
      }
  } else if (br == 1) {
    cin = 2;
    wv[0] = (double)w2[uu * 2]; wv[1] = (double)w2[uu * 2 + 1];
    mu = wv[0] * mom[3] + wv[1] * mom[10];
    E2 = wv[0] * wv[0] * mom[50] + 2.0 * wv[0] * wv[1] * mom[51] + wv[1] * wv[1] * mom[52];
  } else if (br == 2) {
    cin = 2;
    wv[0] = (double)w3[uu * 2]; wv[1] = (double)w3[uu * 2 + 1];
    mu = wv[0] * mom[4] + wv[1] * mom[11];
    E2 = wv[0] * wv[0] * mom[53] + 2.0 * wv[0] * wv[1] * mom[54] + wv[1] * wv[1] * mom[55];
  } else {
    cin = 4;
    const int m1i[4] = {0, 1, 12, 13};
    const int S[4][4] = {{14, 15, 56, 57}, {15, 22, 58, 59}, {56, 58, 60, 61}, {57, 59, 61, 62}};
    for (int c = 0; c < 4; c++) wv[c] = (double)w4[uu * 4 + c];
    for (int c = 0; c < 4; c++) mu += wv[c] * mom[m1i[c]];
    for (int i = 0; i < 4; i++)
      for (int j = 0; j < 4; j++) E2 += wv[i] * wv[j] * mom[S[i][j]];
  }
  const double gmv = (double)gm_[br * 16 + uu];
  const double btv = (double)bt_[br * 16 + uu];
  const double var = E2 - mu * mu;
  const double invs = 1.0 / sqrt(var + (double)1e-3f);
  const double scale = gmv * invs;

  // packed (unit-pair) layout writes
  const int half = uu & 1, p = uu >> 1;
  for (int c = 0; c < cin; c++) {
    int pidx;
    if      (br == 0) pidx = p * 8 + c;
    else if (br == 1) pidx = 64 + p * 2 + c;
    else if (br == 2) pidx = 80 + p * 2 + c;
    else              pidx = 96 + p * 4 + c;
    g_coeff[pidx * 2 + half] = (float)(wv[c] * scale);
  }
  g_coeff[256 + br * 16 + uu] = (float)(btv - mu * scale);  // == (128 + ch/2)*2 + (ch&1)
}

// ---------------------------------------------------------------------------
__global__ __launch_bounds__(WARPS_C * 32, 5)
void main_kernel(const float* __restrict__ feats, const int* __restrict__ nump,
                 const int* __restrict__ coors, float* __restrict__ out, int nP) {
  __shared__ float s_y[WARPS_C][MPTS * YSTRIDE];          // 34816 B
  __shared__ __align__(16) float s_stage[WARPS_C][2][288]; // 9216 B (double buffer)
  __shared__ __align__(16) u64 s_cf[160];                  // 1280 B packed coeffs
  const int tid  = threadIdx.x;
  const int warp = tid >> 5;
  const int lane = tid & 31;

#pragma unroll
  for (int i = tid; i < 160; i += WARPS_C * 32)
    s_cf[i] = reinterpret_cast<const u64*>(g_coeff)[i];
  __syncthreads();

  const int gw      = blockIdx.x * WARPS_C + warp;   // global warp id
  const int WSTRIDE = BLOCKS_C * WARPS_C;
  float* sm  = s_y[warp];
  float* row = sm + lane * YSTRIDE;

  // prologue: prefetch first pillar + its scalars
  int   np_c = 1; float cx_c = 0.f, cy_c = 0.f;
  if (gw < nP) {
    const float4* src = reinterpret_cast<const float4*>(feats + (size_t)gw * 288);
    unsigned base = (unsigned)__cvta_generic_to_shared(&s_stage[warp][0][0]);
    cp16(base + lane * 16, src + lane);
    cp16(base + (lane + 32) * 16, src + lane + 32);
    if (lane < 8) cp16(base + (lane + 64) * 16, src + lane + 64);
    np_c = nump[gw];
    cx_c = (float)coors[gw * 4 + 3] * VXc + XOFF;
    cy_c = (float)coors[gw * 4 + 2] * VYc + YOFF;
  }
  asm volatile("cp.async.commit_group;");

  int buf = 0;
  for (int n = gw; n < nP; n += WSTRIDE) {
    // prefetch next pillar into the other buffer + its scalars
    const int nn = n + WSTRIDE;
    int np_n = 1; float cx_n = 0.f, cy_n = 0.f;
    if (nn < nP) {
      const float4* src = reinterpret_cast<const float4*>(feats + (size_t)nn * 288);
      unsigned base = (unsigned)__cvta_generic_to_shared(&s_stage[warp][buf ^ 1][0]);
      cp16(base + lane * 16, src + lane);
      cp16(base + (lane + 32) * 16, src + lane + 32);
      if (lane < 8) cp16(base + (lane + 64) * 16, src + lane + 64);
      np_n = nump[nn];
      cx_n = (float)coors[nn * 4 + 3] * VXc + XOFF;
      cy_n = (float)coors[nn * 4 + 2] * VYc + YOFF;
    }
    asm volatile("cp.async.commit_group;");
    asm volatile("cp.async.wait_group 1;");
    __syncwarp();

    const float* sb = s_stage[warp][buf];
    float f[9];
#pragma unroll
    for (int c = 0; c < 9; c++) f[c] = sb[lane * 9 + c];

    float v[14];
    make_feat(f, np_c, cx_c, cy_c, lane, v);

    u64 acc[8];
    // ---- branch 0: 8 unit-pairs, 8 inputs ----
    {
      const float x1[8] = {v[0], v[1], v[2], v[5], v[6], v[7], v[8], v[9]};
      u64 xp[8];
#pragma unroll
      for (int c = 0; c < 8; c++) xp[c] = pk2(x1[c], x1[c]);
#pragma unroll
      for (int pp = 0; pp < 4; pp++) {
        ulonglong2 sh = *reinterpret_cast<const ulonglong2*>(&s_cf[128 + 2 * pp]);
        acc[2 * pp] = sh.x; acc[2 * pp + 1] = sh.y;
      }
#pragma unroll
      for (int p = 0; p < 8; p++) {
#pragma unroll
        for (int c = 0; c < 8; c += 2) {
          ulonglong2 w = *reinterpret_cast<const ulonglong2*>(&s_cf[p * 8 + c]);
          acc[p] = ffma2(xp[c], w.x, acc[p]);
          acc[p] = ffma2(xp[c + 1], w.y, acc[p]);
        }
      }
#pragma unroll
      for (int pp = 0; pp < 4; pp++) {
        ulonglong2 o; o.x = acc[2 * pp]; o.y = acc[2 * pp + 1];
        *reinterpret_cast<ulonglong2*>(row + 4 * pp) = o;
      }
    }
    // ---- branch 1: inputs (v3, v10) ----
    {
      u64 a0 = pk2(v[3], v[3]), a1 = pk2(v[10], v[10]);
#pragma unroll
      for (int pp = 0; pp < 4; pp++) {
        ulonglong2 sh = *reinterpret_cast<const ulonglong2*>(&s_cf[136 + 2 * pp]);
        acc[2 * pp] = sh.x; acc[2 * pp + 1] = sh.y;
      }
#pragma unroll
      for (int p = 0; p < 8; p++) {
        ulonglong2 w = *reinterpret_cast<const ulonglong2*>(&s_cf[64 + 2 * p]);
        acc[p] = ffma2(a0, w.x, acc[p]);
        acc[p] = ffma2(a1, w.y, acc[p]);
      }
#pragma unroll
      for (int pp = 0; pp < 4; pp++) {
        ulonglong2 o; o.x = acc[2 * pp]; o.y = acc[2 * pp + 1];
        *reinterpret_cast<ulonglong2*>(row + 16 + 4 * pp) = o;
      }
    }
    // ---- branch 2: inputs (v4, v11) ----
    {
      u64 a0 = pk2(v[4], v[4]), a1 = pk2(v[11], v[11]);
#pragma unroll
      for (int pp = 0; pp < 4; pp++) {
        ulonglong2 sh = *reinterpret_cast<const ulonglong2*>(&s_cf[144 + 2 * pp]);
        acc[2 * pp] = sh.x; acc[2 * pp + 1] = sh.y;
      }
#pragma unroll
      for (int p = 0; p < 8; p++) {
        ulonglong2 w = *reinterpret_cast<const ulonglong2*>(&s_cf[80 + 2 * p]);
        acc[p] = ffma2(a0, w.x, acc[p]);
        acc[p] = ffma2(a1, w.y, acc[p]);
      }
#pragma unroll
      for (int pp = 0; pp < 4; pp++) {
        ulonglong2 o; o.x = acc[2 * pp]; o.y = acc[2 * pp + 1];
        *reinterpret_cast<ulonglong2*>(row + 32 + 4 * pp) = o;
      }
    }
    // ---- branch 3: inputs (v0, v1, v12, v13) ----
    {
      u64 a0 = pk2(v[0], v[0]), a1 = pk2(v[1], v[1]);
      u64 a2 = pk2(v[12], v[12]), a3 = pk2(v[13], v[13]);
#pragma unroll
      for (int pp = 0; pp < 4; pp++) {
        ulonglong2 sh = *reinterpret_cast<const ulonglong2*>(&s_cf[152 + 2 * pp]);
        acc[2 * pp] = sh.x; acc[2 * pp + 1] = sh.y;
      }
#pragma unroll
      for (int p = 0; p < 8; p++) {
        ulonglong2 w01 = *reinterpret_cast<const ulonglong2*>(&s_cf[96 + 4 * p]);
        ulonglong2 w23 = *reinterpret_cast<const ulonglong2*>(&s_cf[96 + 4 * p + 2]);
        acc[p] = ffma2(a0, w01.x, acc[p]);
        acc[p] = ffma2(a1, w01.y, acc[p]);
        acc[p] = ffma2(a2, w23.x, acc[p]);
        acc[p] = ffma2(a3, w23.y, acc[p]);
      }
#pragma unroll
      for (int pp = 0; pp < 4; pp++) {
        ulonglong2 o; o.x = acc[2 * pp]; o.y = acc[2 * pp + 1];
        *reinterpret_cast<ulonglong2*>(row + 48 + 4 * pp) = o;
      }
    }
    __syncwarp();

    // per-channel max: lane pair (g = lane>>1) covers channel quad 4g..4g+3;
    // each lane scans 16 rows (its parity), then one shuffle exchange.
    {
      const int g4  = (lane >> 1) * 4;
      const int par = lane & 1;
      float m0 = -1e30f, m1 = -1e30f, m2 = -1e30f, m3 = -1e30f;
#pragma unroll
      for (int i = 0; i < 16; i++) {
        const int m = par + 2 * i;
        const float4 q = *reinterpret_cast<const float4*>(sm + m * YSTRIDE + g4);
        m0 = fmaxf(m0, q.x); m1 = fmaxf(m1, q.y);
        m2 = fmaxf(m2, q.z); m3 = fmaxf(m3, q.w);
      }
      const float k0 = par ? m2 : m0, k1 = par ? m3 : m1;
      const float s0 = par ? m0 : m2, s1 = par ? m1 : m3;
      const float r0 = __shfl_xor_sync(0xffffffffu, s0, 1);
      const float r1 = __shfl_xor_sync(0xffffffffu, s1, 1);
      float2 o;
      o.x = fmaxf(fmaxf(k0, r0), 0.f);   // relu commutes with max
      o.y = fmaxf(fmaxf(k1, r1), 0.f);
      reinterpret_cast<float2*>(out + (size_t)n * 64)[lane] = o;
    }
    __syncwarp();  // all lanes done with s_y / stage buf before next refill

    buf ^= 1;
    np_c = np_n; cx_c = cx_n; cy_c = cy_n;
  }
}

// ---------------------------------------------------------------------------
extern "C" void kernel_launch(void* const* d_in, const int* in_sizes, int n_in,
                              void* d_out, int out_size) {
  const float* feats = (const float*)d_in[0];
  const float* w1    = (const float*)d_in[1];
  const float* w2    = (const float*)d_in[2];
  const float* w3    = (const float*)d_in[3];
  const float* w4    = (const float*)d_in[4];
  const float* gmm   = (const float*)d_in[5];
  const float* bta   = (const float*)d_in[6];
  const int*   nump  = (const int*)d_in[7];
  const int*   coors = (const int*)d_in[8];
  float*       out   = (float*)d_out;

  const int nP = in_sizes[7];
  const double tot = (double)nP * (double)MPTS;

  moments_kernel<<<GRID_A, WARPS_A * 32>>>(feats, nump, coors, nP);
  finalize_kernel<<<1, 64>>>(w1, w2, w3, w4, gmm, bta, tot);
  main_kernel<<<BLOCKS_C, WARPS_C * 32>>>(feats, nump, coors, out, nP);
}